// round 6
// baseline (speedup 1.0000x reference)
#include <cuda_runtime.h>
#include <cstdint>

#define N_NODES 100000
#define N_EDGES 1600000
#define IN_CH   128
#define HID     128
#define OUT_CH  64

#define SCAN_BLK 1024                       // elements per scan block
#define N_SBLK   ((N_NODES + SCAN_BLK - 1) / SCAN_BLK)   // 98

// ---------------- scratch (device globals: allocation-free) ----------------
__device__ int   g_cnt [N_NODES];                    // in-degree (excl. self-loop)
__device__ int   g_off [N_NODES];                    // CSR row offsets (exclusive)
__device__ int   g_cur [N_NODES];                    // fill cursors
__device__ int   g_bsum[N_SBLK];                     // scan block sums -> prefixes
__device__ float g_dinv[N_NODES];
__device__ int   g_col [N_EDGES];                    // CSR column (src) lists
__device__ float g_hs  [(size_t)N_NODES * HID];      // (x @ W1) * dinv[row]
__device__ float g_z   [(size_t)N_NODES * HID];      // relu layer-1 output
__device__ float g_h2s [(size_t)N_NODES * OUT_CH];   // (z @ W2) * dinv[row]

// ---------------- packed f32x2 helpers ----------------
__device__ __forceinline__ void fma2(uint64_t& d, uint64_t a, uint64_t b) {
    asm("fma.rn.f32x2 %0, %1, %2, %0;" : "+l"(d) : "l"(a), "l"(b));
}
__device__ __forceinline__ uint64_t pack2(float v) {
    uint64_t r;
    asm("mov.b64 %0, {%1, %1};" : "=l"(r) : "f"(v));
    return r;
}
__device__ __forceinline__ float2 unpack2(uint64_t p) {
    float2 r;
    asm("mov.b64 {%0, %1}, %2;" : "=f"(r.x), "=f"(r.y) : "l"(p));
    return r;
}

// ---------------- init (graph replays => counters must reset) --------------
__global__ void k_init() {
    int i = blockIdx.x * blockDim.x + threadIdx.x;
    if (i < N_NODES) g_cnt[i] = 0;
}

// ---------------- degree count ----------------
__global__ void k_cnt(const int* __restrict__ ei) {
    int e = blockIdx.x * blockDim.x + threadIdx.x;
    if (e < N_EDGES) atomicAdd(&g_cnt[__ldg(&ei[N_EDGES + e])], 1);
}

// ---------------- scan stage 1: per-block sums ----------------
__global__ void k_blocksum() {           // 256 threads, 4 elems/thread
    __shared__ int sh[256];
    int t = threadIdx.x, b = blockIdx.x;
    int base = b * SCAN_BLK + t * 4;
    int s = 0;
#pragma unroll
    for (int k = 0; k < 4; k++) {
        int i = base + k;
        if (i < N_NODES) s += g_cnt[i];
    }
    sh[t] = s;
    __syncthreads();
    for (int st = 128; st > 0; st >>= 1) {
        if (t < st) sh[t] += sh[t + st];
        __syncthreads();
    }
    if (t == 0) g_bsum[b] = sh[0];
}

// ---------------- scan stage 2: serial exclusive scan of block sums --------
__global__ void k_bscan() {
    if (threadIdx.x == 0) {
        int acc = 0;
        for (int b = 0; b < N_SBLK; b++) {
            int v = g_bsum[b];
            g_bsum[b] = acc;
            acc += v;
        }
    }
}

// ---------------- scan stage 3: offsets + cursors + dinv ----------------
__global__ void k_offsets() {            // 256 threads, 4 elems/thread
    __shared__ int sh[256];
    int t = threadIdx.x, b = blockIdx.x;
    int base = b * SCAN_BLK + t * 4;
    int v[4];
    int s = 0;
#pragma unroll
    for (int k = 0; k < 4; k++) {
        int i = base + k;
        v[k] = (i < N_NODES) ? g_cnt[i] : 0;
        s += v[k];
    }
    sh[t] = s;
    __syncthreads();
    // Hillis-Steele inclusive scan over 256 thread sums
    for (int st = 1; st < 256; st <<= 1) {
        int add = (t >= st) ? sh[t - st] : 0;
        __syncthreads();
        sh[t] += add;
        __syncthreads();
    }
    int pre = g_bsum[b] + (t > 0 ? sh[t - 1] : 0);   // exclusive prefix for elem 0
#pragma unroll
    for (int k = 0; k < 4; k++) {
        int i = base + k;
        if (i < N_NODES) {
            g_off[i]  = pre;
            g_cur[i]  = pre;
            g_dinv[i] = rsqrtf((float)(v[k] + 1));   // +1 self-loop
        }
        pre += v[k];
    }
}

// ---------------- CSR fill: col[cur[d]++] = src ----------------
__global__ void k_fill(const int* __restrict__ ei) {
    int e = blockIdx.x * blockDim.x + threadIdx.x;
    if (e >= N_EDGES) return;
    int s = __ldg(&ei[e]);
    int d = __ldg(&ei[N_EDGES + e]);
    int slot = atomicAdd(&g_cur[d], 1);
    g_col[slot] = s;
}

// ---------------- GEMM: H[N,FOUT] = (X[N,128] @ W[128,FOUT]) * dinv[row] ----
// Packed-FP32 (fma.rn.f32x2) mainloop: each thread owns NPT nodes x 8 cols
// (4 packed accumulators per node). 256 threads/block.
#define XSTRIDE 132   // padded X row (floats): conflict-free, 16B-aligned

template<int FOUT, int NPT>
__global__ void k_gemm(const float* __restrict__ X, const float* __restrict__ W,
                       float* __restrict__ H) {
    constexpr int CG = FOUT / 8;      // column groups of 8
    constexpr int NG = 256 / CG;      // node groups
    constexpr int BN = NG * NPT;      // nodes per block
    extern __shared__ float sm[];
    float* Wsh = sm;                  // 128*FOUT floats
    float* Xsh = sm + 128 * FOUT;     // BN*XSTRIDE floats

    const int tid = threadIdx.x;
    const int n0  = blockIdx.x * BN;

    for (int i = tid; i < 128 * FOUT / 4; i += 256)
        ((float4*)Wsh)[i] = ((const float4*)W)[i];

    for (int idx = tid; idx < BN * 32; idx += 256) {
        int row = idx >> 5, c4 = idx & 31;
        float4 v = make_float4(0.f, 0.f, 0.f, 0.f);
        if (n0 + row < N_NODES)
            v = ((const float4*)X)[(size_t)(n0 + row) * 32 + c4];
        *(float4*)&Xsh[row * XSTRIDE + c4 * 4] = v;
    }
    __syncthreads();

    const int cg = tid % CG;          // which 8-col group
    const int ng = tid / CG;          // which node group
    uint64_t acc[NPT][4];
#pragma unroll
    for (int m = 0; m < NPT; m++)
#pragma unroll
        for (int c = 0; c < 4; c++) acc[m][c] = 0ull;   // two packed 0.0f

    const float* xrow = &Xsh[ng * NPT * XSTRIDE];
#pragma unroll 4
    for (int k = 0; k < 128; k++) {
        // 8 W coefficients = 4 packed column pairs (adjacent cols)
        ulonglong2 w01 = *(const ulonglong2*)&Wsh[k * FOUT + 8 * cg];
        ulonglong2 w23 = *(const ulonglong2*)&Wsh[k * FOUT + 8 * cg + 4];
#pragma unroll
        for (int m = 0; m < NPT; m++) {
            uint64_t xp = pack2(xrow[m * XSTRIDE + k]);
            fma2(acc[m][0], xp, w01.x);
            fma2(acc[m][1], xp, w01.y);
            fma2(acc[m][2], xp, w23.x);
            fma2(acc[m][3], xp, w23.y);
        }
    }

#pragma unroll
    for (int m = 0; m < NPT; m++) {
        int row = n0 + ng * NPT + m;
        if (row < N_NODES) {
            float di = g_dinv[row];
            float2 p0 = unpack2(acc[m][0]), p1 = unpack2(acc[m][1]);
            float2 p2 = unpack2(acc[m][2]), p3 = unpack2(acc[m][3]);
            float4 a, b;
            a.x = p0.x * di; a.y = p0.y * di; a.z = p1.x * di; a.w = p1.y * di;
            b.x = p2.x * di; b.y = p2.y * di; b.z = p3.x * di; b.w = p3.y * di;
            float4* dst = &((float4*)H)[(size_t)row * (FOUT / 4) + 2 * cg];
            dst[0] = a;
            dst[1] = b;
        }
    }
}

// ---------------- pull layer 1: z = relu(dinv[d]*(sum hs[s] + hs[d]) + b1) --
// one warp per destination row; lane covers 4 of 128 floats.
// Column indices loaded lane-parallel (one coalesced LDG per 32 edges),
// broadcast to the warp via shfl.
__global__ void k_pull1(const float* __restrict__ b1) {
    int w = (blockIdx.x * blockDim.x + threadIdx.x) >> 5;
    if (w >= N_NODES) return;
    int lane = threadIdx.x & 31;
    int cnt = g_cnt[w];
    int off = g_off[w];

    float4 acc = ((const float4*)g_hs)[(size_t)w * 32 + lane];  // self-loop term
    for (int base = 0; base < cnt; base += 32) {
        int rem = cnt - base;
        int m = rem < 32 ? rem : 32;
        int ci = (lane < m) ? __ldg(&g_col[off + base + lane]) : 0;
        int j = 0;
        for (; j + 8 <= m; j += 8) {
            int s[8];
#pragma unroll
            for (int u = 0; u < 8; u++) s[u] = __shfl_sync(0xffffffffu, ci, j + u);
            float4 v[8];
#pragma unroll
            for (int u = 0; u < 8; u++)
                v[u] = ((const float4*)g_hs)[(size_t)s[u] * 32 + lane];
#pragma unroll
            for (int u = 0; u < 8; u++) {
                acc.x += v[u].x; acc.y += v[u].y; acc.z += v[u].z; acc.w += v[u].w;
            }
        }
        for (; j < m; j++) {
            int s = __shfl_sync(0xffffffffu, ci, j);
            float4 v = ((const float4*)g_hs)[(size_t)s * 32 + lane];
            acc.x += v.x; acc.y += v.y; acc.z += v.z; acc.w += v.w;
        }
    }
    float di = g_dinv[w];
    float4 b = ((const float4*)b1)[lane];
    float4 z;
    z.x = fmaxf(fmaf(di, acc.x, b.x), 0.f);
    z.y = fmaxf(fmaf(di, acc.y, b.y), 0.f);
    z.z = fmaxf(fmaf(di, acc.z, b.z), 0.f);
    z.w = fmaxf(fmaf(di, acc.w, b.w), 0.f);
    ((float4*)g_z)[(size_t)w * 32 + lane] = z;
}

// ---------------- pull layer 2: out = dinv[d]*(sum h2s[s] + h2s[d]) + b2 ----
// one warp per destination row; lane covers 2 of 64 floats; shfl index bcast
__global__ void k_pull2(const float* __restrict__ b2, float* __restrict__ out) {
    int w = (blockIdx.x * blockDim.x + threadIdx.x) >> 5;
    if (w >= N_NODES) return;
    int lane = threadIdx.x & 31;
    int cnt = g_cnt[w];
    int off = g_off[w];

    float2 acc = ((const float2*)g_h2s)[(size_t)w * 32 + lane];  // self-loop
    for (int base = 0; base < cnt; base += 32) {
        int rem = cnt - base;
        int m = rem < 32 ? rem : 32;
        int ci = (lane < m) ? __ldg(&g_col[off + base + lane]) : 0;
        int j = 0;
        for (; j + 8 <= m; j += 8) {
            int s[8];
#pragma unroll
            for (int u = 0; u < 8; u++) s[u] = __shfl_sync(0xffffffffu, ci, j + u);
            float2 v[8];
#pragma unroll
            for (int u = 0; u < 8; u++)
                v[u] = ((const float2*)g_h2s)[(size_t)s[u] * 32 + lane];
#pragma unroll
            for (int u = 0; u < 8; u++) { acc.x += v[u].x; acc.y += v[u].y; }
        }
        for (; j < m; j++) {
            int s = __shfl_sync(0xffffffffu, ci, j);
            float2 v = ((const float2*)g_h2s)[(size_t)s * 32 + lane];
            acc.x += v.x; acc.y += v.y;
        }
    }
    float di = g_dinv[w];
    float2 b = ((const float2*)b2)[lane];
    float2 o;
    o.x = fmaf(di, acc.x, b.x);
    o.y = fmaf(di, acc.y, b.y);
    ((float2*)out)[(size_t)w * 32 + lane] = o;
}

// ---------------- launch ----------------
extern "C" void kernel_launch(void* const* d_in, const int* in_sizes, int n_in,
                              void* d_out, int out_size) {
    const float* x  = (const float*)d_in[0];
    const int*   ei = (const int*)  d_in[1];
    const float* W1 = (const float*)d_in[2];
    const float* b1 = (const float*)d_in[3];
    const float* W2 = (const float*)d_in[4];
    const float* b2 = (const float*)d_in[5];
    float* out = (float*)d_out;

    float *hsP, *zP, *h2sP;
    cudaGetSymbolAddress((void**)&hsP,  g_hs);
    cudaGetSymbolAddress((void**)&zP,   g_z);
    cudaGetSymbolAddress((void**)&h2sP, g_h2s);

    const int T = 256;

    // ---- graph build: counts -> CSR offsets (+dinv) -> fill ----
    k_init<<<(N_NODES + T - 1) / T, T>>>();
    k_cnt <<<(N_EDGES + T - 1) / T, T>>>(ei);
    k_blocksum<<<N_SBLK, 256>>>();
    k_bscan<<<1, 32>>>();
    k_offsets<<<N_SBLK, 256>>>();
    k_fill<<<(N_EDGES + T - 1) / T, T>>>(ei);

    // ---- layer 1: hs = (x @ W1) * dinv   (BN = 64 nodes/block) ----
    const int smem1 = (128 * HID + 64 * XSTRIDE) * sizeof(float);
    cudaFuncSetAttribute(k_gemm<HID, 4>, cudaFuncAttributeMaxDynamicSharedMemorySize, smem1);
    k_gemm<HID, 4><<<(N_NODES + 63) / 64, T, smem1>>>(x, W1, hsP);

    // ---- pull + bias + relu -> z ----
    k_pull1<<<(N_NODES * 32 + T - 1) / T, T>>>(b1);

    // ---- layer 2: h2s = (z @ W2) * dinv  (BN = 128 nodes/block) ----
    const int smem2 = (128 * OUT_CH + 128 * XSTRIDE) * sizeof(float);
    cudaFuncSetAttribute(k_gemm<OUT_CH, 4>, cudaFuncAttributeMaxDynamicSharedMemorySize, smem2);
    k_gemm<OUT_CH, 4><<<(N_NODES + 127) / 128, T, smem2>>>(zP, W2, h2sP);

    // ---- pull + bias -> out ----
    k_pull2<<<(N_NODES * 32 + T - 1) / T, T>>>(b2, out);
}

// round 11
// speedup vs baseline: 1.1575x; 1.1575x over previous
#include <cuda_runtime.h>
#include <cuda_fp16.h>
#include <cstdint>

#define N_NODES 100000
#define N_EDGES 1600000
#define IN_CH   128
#define HID     128
#define OUT_CH  64

#define SCAN_BLK 1024                       // elements per scan block
#define N_SBLK   ((N_NODES + SCAN_BLK - 1) / SCAN_BLK)   // 98

// ---------------- scratch (device globals: allocation-free) ----------------
__device__ int    g_cnt [N_NODES];                    // in-degree (excl. self-loop)
__device__ int    g_off [N_NODES];                    // CSR row offsets (exclusive)
__device__ int    g_cur [N_NODES];                    // fill cursors
__device__ int    g_bsum[N_SBLK];                     // scan block sums -> prefixes
__device__ float  g_dinv[N_NODES];
__device__ int    g_col [N_EDGES];                    // CSR column (src) lists
__device__ __half g_hs  [(size_t)N_NODES * HID];      // (x @ W1) * dinv[row], fp16
__device__ float  g_z   [(size_t)N_NODES * HID];      // relu layer-1 output (fp32)
__device__ __half g_h2s [(size_t)N_NODES * OUT_CH];   // (z @ W2) * dinv[row], fp16

// ---------------- packed f32x2 helpers ----------------
__device__ __forceinline__ void fma2(uint64_t& d, uint64_t a, uint64_t b) {
    asm("fma.rn.f32x2 %0, %1, %2, %0;" : "+l"(d) : "l"(a), "l"(b));
}
__device__ __forceinline__ uint64_t pack2(float v) {
    uint64_t r;
    asm("mov.b64 %0, {%1, %1};" : "=l"(r) : "f"(v));
    return r;
}
__device__ __forceinline__ float2 unpack2(uint64_t p) {
    float2 r;
    asm("mov.b64 {%0, %1}, %2;" : "=f"(r.x), "=f"(r.y) : "l"(p));
    return r;
}

// fp16x4 (uint2) -> float4
__device__ __forceinline__ float4 h4f4(uint2 p) {
    __half2 a = *reinterpret_cast<__half2*>(&p.x);
    __half2 b = *reinterpret_cast<__half2*>(&p.y);
    float2 fa = __half22float2(a), fb = __half22float2(b);
    return make_float4(fa.x, fa.y, fb.x, fb.y);
}

// ---------------- init (graph replays => counters must reset) --------------
__global__ void k_init() {
    int i = blockIdx.x * blockDim.x + threadIdx.x;
    if (i < N_NODES) g_cnt[i] = 0;
}

// ---------------- degree count ----------------
__global__ void k_cnt(const int* __restrict__ ei) {
    int e = blockIdx.x * blockDim.x + threadIdx.x;
    if (e < N_EDGES) atomicAdd(&g_cnt[__ldg(&ei[N_EDGES + e])], 1);
}

// ---------------- scan stage 1: per-block sums ----------------
__global__ void k_blocksum() {           // 256 threads, 4 elems/thread
    __shared__ int sh[256];
    int t = threadIdx.x, b = blockIdx.x;
    int base = b * SCAN_BLK + t * 4;
    int s = 0;
#pragma unroll
    for (int k = 0; k < 4; k++) {
        int i = base + k;
        if (i < N_NODES) s += g_cnt[i];
    }
    sh[t] = s;
    __syncthreads();
    for (int st = 128; st > 0; st >>= 1) {
        if (t < st) sh[t] += sh[t + st];
        __syncthreads();
    }
    if (t == 0) g_bsum[b] = sh[0];
}

// ---------------- scan stage 2: serial exclusive scan of block sums --------
__global__ void k_bscan() {
    if (threadIdx.x == 0) {
        int acc = 0;
        for (int b = 0; b < N_SBLK; b++) {
            int v = g_bsum[b];
            g_bsum[b] = acc;
            acc += v;
        }
    }
}

// ---------------- scan stage 3: offsets + cursors + dinv ----------------
__global__ void k_offsets() {            // 256 threads, 4 elems/thread
    __shared__ int sh[256];
    int t = threadIdx.x, b = blockIdx.x;
    int base = b * SCAN_BLK + t * 4;
    int v[4];
    int s = 0;
#pragma unroll
    for (int k = 0; k < 4; k++) {
        int i = base + k;
        v[k] = (i < N_NODES) ? g_cnt[i] : 0;
        s += v[k];
    }
    sh[t] = s;
    __syncthreads();
    // Hillis-Steele inclusive scan over 256 thread sums
    for (int st = 1; st < 256; st <<= 1) {
        int add = (t >= st) ? sh[t - st] : 0;
        __syncthreads();
        sh[t] += add;
        __syncthreads();
    }
    int pre = g_bsum[b] + (t > 0 ? sh[t - 1] : 0);   // exclusive prefix for elem 0
#pragma unroll
    for (int k = 0; k < 4; k++) {
        int i = base + k;
        if (i < N_NODES) {
            g_off[i]  = pre;
            g_cur[i]  = pre;
            g_dinv[i] = rsqrtf((float)(v[k] + 1));   // +1 self-loop
        }
        pre += v[k];
    }
}

// ---------------- CSR fill: col[cur[d]++] = src ----------------
__global__ void k_fill(const int* __restrict__ ei) {
    int e = blockIdx.x * blockDim.x + threadIdx.x;
    if (e >= N_EDGES) return;
    int s = __ldg(&ei[e]);
    int d = __ldg(&ei[N_EDGES + e]);
    int slot = atomicAdd(&g_cur[d], 1);
    g_col[slot] = s;
}

// ---------------- GEMM: H[N,FOUT] = fp16((X[N,128] @ W[128,FOUT])*dinv[row])
// Packed-FP32 (fma.rn.f32x2) mainloop: each thread owns NPT nodes x 8 cols
// (4 packed accumulators per node). 256 threads/block. Output fp16.
#define XSTRIDE 132   // padded X row (floats): conflict-free, 16B-aligned

template<int FOUT, int NPT>
__global__ void k_gemm(const float* __restrict__ X, const float* __restrict__ W,
                       __half* __restrict__ H) {
    constexpr int CG = FOUT / 8;      // column groups of 8
    constexpr int NG = 256 / CG;      // node groups
    constexpr int BN = NG * NPT;      // nodes per block
    extern __shared__ float sm[];
    float* Wsh = sm;                  // 128*FOUT floats
    float* Xsh = sm + 128 * FOUT;     // BN*XSTRIDE floats

    const int tid = threadIdx.x;
    const int n0  = blockIdx.x * BN;

    for (int i = tid; i < 128 * FOUT / 4; i += 256)
        ((float4*)Wsh)[i] = ((const float4*)W)[i];

    for (int idx = tid; idx < BN * 32; idx += 256) {
        int row = idx >> 5, c4 = idx & 31;
        float4 v = make_float4(0.f, 0.f, 0.f, 0.f);
        if (n0 + row < N_NODES)
            v = ((const float4*)X)[(size_t)(n0 + row) * 32 + c4];
        *(float4*)&Xsh[row * XSTRIDE + c4 * 4] = v;
    }
    __syncthreads();

    const int cg = tid % CG;          // which 8-col group
    const int ng = tid / CG;          // which node group
    uint64_t acc[NPT][4];
#pragma unroll
    for (int m = 0; m < NPT; m++)
#pragma unroll
        for (int c = 0; c < 4; c++) acc[m][c] = 0ull;   // two packed 0.0f

    const float* xrow = &Xsh[ng * NPT * XSTRIDE];
#pragma unroll 4
    for (int k = 0; k < 128; k++) {
        // 8 W coefficients = 4 packed column pairs (adjacent cols)
        ulonglong2 w01 = *(const ulonglong2*)&Wsh[k * FOUT + 8 * cg];
        ulonglong2 w23 = *(const ulonglong2*)&Wsh[k * FOUT + 8 * cg + 4];
#pragma unroll
        for (int m = 0; m < NPT; m++) {
            uint64_t xp = pack2(xrow[m * XSTRIDE + k]);
            fma2(acc[m][0], xp, w01.x);
            fma2(acc[m][1], xp, w01.y);
            fma2(acc[m][2], xp, w23.x);
            fma2(acc[m][3], xp, w23.y);
        }
    }

#pragma unroll
    for (int m = 0; m < NPT; m++) {
        int row = n0 + ng * NPT + m;
        if (row < N_NODES) {
            float di = g_dinv[row];
            float2 p0 = unpack2(acc[m][0]), p1 = unpack2(acc[m][1]);
            float2 p2 = unpack2(acc[m][2]), p3 = unpack2(acc[m][3]);
            __half2 q0 = __floats2half2_rn(p0.x * di, p0.y * di);
            __half2 q1 = __floats2half2_rn(p1.x * di, p1.y * di);
            __half2 q2 = __floats2half2_rn(p2.x * di, p2.y * di);
            __half2 q3 = __floats2half2_rn(p3.x * di, p3.y * di);
            uint4 w;
            w.x = *(uint32_t*)&q0; w.y = *(uint32_t*)&q1;
            w.z = *(uint32_t*)&q2; w.w = *(uint32_t*)&q3;
            ((uint4*)(H + (size_t)row * FOUT))[cg] = w;   // 8 halfs = 16B
        }
    }
}

// ---------------- pull layer 1: z = relu(dinv[d]*(sum hs[s] + hs[d]) + b1) --
// one warp per destination row; lane covers 4 of 128 halfs (8B loads).
// Column indices loaded lane-parallel, broadcast via shfl.
__global__ void k_pull1(const float* __restrict__ b1) {
    int w = (blockIdx.x * blockDim.x + threadIdx.x) >> 5;
    if (w >= N_NODES) return;
    int lane = threadIdx.x & 31;
    int cnt = g_cnt[w];
    int off = g_off[w];
    const uint2* hsv = (const uint2*)g_hs;   // 4 halfs per uint2, 32 per row

    float4 acc = h4f4(__ldg(&hsv[(size_t)w * 32 + lane]));  // self-loop term
    for (int base = 0; base < cnt; base += 32) {
        int rem = cnt - base;
        int m = rem < 32 ? rem : 32;
        int ci = (lane < m) ? __ldg(&g_col[off + base + lane]) : 0;
        int j = 0;
        for (; j + 8 <= m; j += 8) {
            int s[8];
#pragma unroll
            for (int u = 0; u < 8; u++) s[u] = __shfl_sync(0xffffffffu, ci, j + u);
            uint2 v[8];
#pragma unroll
            for (int u = 0; u < 8; u++)
                v[u] = __ldg(&hsv[(size_t)s[u] * 32 + lane]);
#pragma unroll
            for (int u = 0; u < 8; u++) {
                float4 f = h4f4(v[u]);
                acc.x += f.x; acc.y += f.y; acc.z += f.z; acc.w += f.w;
            }
        }
        for (; j < m; j++) {
            int s = __shfl_sync(0xffffffffu, ci, j);
            float4 f = h4f4(__ldg(&hsv[(size_t)s * 32 + lane]));
            acc.x += f.x; acc.y += f.y; acc.z += f.z; acc.w += f.w;
        }
    }
    float di = g_dinv[w];
    float4 b = ((const float4*)b1)[lane];
    float4 z;
    z.x = fmaxf(fmaf(di, acc.x, b.x), 0.f);
    z.y = fmaxf(fmaf(di, acc.y, b.y), 0.f);
    z.z = fmaxf(fmaf(di, acc.z, b.z), 0.f);
    z.w = fmaxf(fmaf(di, acc.w, b.w), 0.f);
    ((float4*)g_z)[(size_t)w * 32 + lane] = z;
}

// ---------------- pull layer 2: out = dinv[d]*(sum h2s[s] + h2s[d]) + b2 ----
// TWO rows per warp (half-warp per row): 16 lanes x 4 halfs = 64 halfs/row.
// Index loads lane-parallel within the half-warp, broadcast via masked shfl.
__global__ void k_pull2(const float* __restrict__ b2, float* __restrict__ out) {
    int gw = (blockIdx.x * blockDim.x + threadIdx.x) >> 5;   // warp id
    int lane = threadIdx.x & 31;
    int half = lane >> 4;                 // 0 or 1: which row in this warp
    int l16  = lane & 15;                 // lane within half-warp
    int w = gw * 2 + half;                // destination row
    if (w >= N_NODES) return;
    int cnt = g_cnt[w];
    int off = g_off[w];
    const uint2* hv = (const uint2*)g_h2s;   // 4 halfs per uint2, 16 per row
    unsigned hmask = half ? 0xffff0000u : 0x0000ffffu;

    float4 acc = h4f4(__ldg(&hv[(size_t)w * 16 + l16]));   // self-loop term
    for (int base = 0; base < cnt; base += 16) {
        int rem = cnt - base;
        int m = rem < 16 ? rem : 16;
        int ci = (l16 < m) ? __ldg(&g_col[off + base + l16]) : 0;
        int j = 0;
        for (; j + 8 <= m; j += 8) {
            int s[8];
#pragma unroll
            for (int u = 0; u < 8; u++)
                s[u] = __shfl_sync(hmask, ci, half * 16 + j + u);
            uint2 v[8];
#pragma unroll
            for (int u = 0; u < 8; u++)
                v[u] = __ldg(&hv[(size_t)s[u] * 16 + l16]);
#pragma unroll
            for (int u = 0; u < 8; u++) {
                float4 f = h4f4(v[u]);
                acc.x += f.x; acc.y += f.y; acc.z += f.z; acc.w += f.w;
            }
        }
        for (; j < m; j++) {
            int s = __shfl_sync(hmask, ci, half * 16 + j);
            float4 f = h4f4(__ldg(&hv[(size_t)s * 16 + l16]));
            acc.x += f.x; acc.y += f.y; acc.z += f.z; acc.w += f.w;
        }
    }
    float di = g_dinv[w];
    float4 b = ((const float4*)b2)[l16];
    float4 o;
    o.x = fmaf(di, acc.x, b.x);
    o.y = fmaf(di, acc.y, b.y);
    o.z = fmaf(di, acc.z, b.z);
    o.w = fmaf(di, acc.w, b.w);
    ((float4*)out)[(size_t)w * 16 + l16] = o;
}

// ---------------- launch ----------------
extern "C" void kernel_launch(void* const* d_in, const int* in_sizes, int n_in,
                              void* d_out, int out_size) {
    const float* x  = (const float*)d_in[0];
    const int*   ei = (const int*)  d_in[1];
    const float* W1 = (const float*)d_in[2];
    const float* b1 = (const float*)d_in[3];
    const float* W2 = (const float*)d_in[4];
    const float* b2 = (const float*)d_in[5];
    float* out = (float*)d_out;

    __half *hsP, *h2sP;
    float  *zP;
    cudaGetSymbolAddress((void**)&hsP,  g_hs);
    cudaGetSymbolAddress((void**)&zP,   g_z);
    cudaGetSymbolAddress((void**)&h2sP, g_h2s);

    const int T = 256;

    // ---- graph build: counts -> CSR offsets (+dinv) -> fill ----
    k_init<<<(N_NODES + T - 1) / T, T>>>();
    k_cnt <<<(N_EDGES + T - 1) / T, T>>>(ei);
    k_blocksum<<<N_SBLK, 256>>>();
    k_bscan<<<1, 32>>>();
    k_offsets<<<N_SBLK, 256>>>();
    k_fill<<<(N_EDGES + T - 1) / T, T>>>(ei);

    // ---- layer 1: hs = fp16((x @ W1) * dinv)   (BN = 64 nodes/block) ----
    const int smem1 = (128 * HID + 64 * XSTRIDE) * sizeof(float);
    cudaFuncSetAttribute(k_gemm<HID, 4>, cudaFuncAttributeMaxDynamicSharedMemorySize, smem1);
    k_gemm<HID, 4><<<(N_NODES + 63) / 64, T, smem1>>>(x, W1, hsP);

    // ---- pull + bias + relu -> z (fp32) ----
    k_pull1<<<(N_NODES * 32 + T - 1) / T, T>>>(b1);

    // ---- layer 2: h2s = fp16((z @ W2) * dinv)  (BN = 128 nodes/block) ----
    const int smem2 = (128 * OUT_CH + 128 * XSTRIDE) * sizeof(float);
    cudaFuncSetAttribute(k_gemm<OUT_CH, 4>, cudaFuncAttributeMaxDynamicSharedMemorySize, smem2);
    k_gemm<OUT_CH, 4><<<(N_NODES + 127) / 128, T, smem2>>>(zP, W2, h2sP);

    // ---- pull + bias -> out (2 rows per warp) ----
    k_pull2<<<((N_NODES + 1) / 2 * 32 + T - 1) / T, T>>>(b2, out);
}